// round 8
// baseline (speedup 1.0000x reference)
#include <cuda_runtime.h>
#include <cstdint>
#include <math.h>

#define B_ 128
#define T_ 100
#define E_ 128
#define F_ 700
#define S_ 400
#define V_ 10000

// ---------------- static device scratch (no allocations allowed) ----------------
static __device__ __align__(16) float g_fh[B_ * F_];
static __device__ __align__(16) float g_fc[B_ * F_];
static __device__ __align__(16) float g_sh[B_ * S_];
static __device__ __align__(16) float g_sc[B_ * S_];
static __device__ __align__(16) float g_z[B_ * 4 * F_];          // gate pre-activations (max 128x2800)
static __device__ __align__(16) float g_outs[B_ * T_ * F_];      // fh outputs, row = b*T + t  (35.8 MB)

// ---------------- helpers ----------------
__device__ __forceinline__ uint32_t f2tf32(float x) {
    uint32_t r;
    asm("cvt.rna.tf32.f32 %0, %1;" : "=r"(r) : "f"(x));
    return r;
}

// split x into hi (tf32) + lo (tf32 of residual): 3xTF32 emulation of fp32
__device__ __forceinline__ void f2tf32_split(float x, uint32_t& hi, uint32_t& lo) {
    hi = f2tf32(x);
    lo = f2tf32(x - __uint_as_float(hi));
}

__device__ __forceinline__ void mma_tf32(float* d, const uint32_t* a, const uint32_t* b) {
    asm volatile(
        "mma.sync.aligned.m16n8k8.row.col.f32.tf32.tf32.f32 "
        "{%0,%1,%2,%3}, {%4,%5,%6,%7}, {%8,%9}, {%0,%1,%2,%3};\n"
        : "+f"(d[0]), "+f"(d[1]), "+f"(d[2]), "+f"(d[3])
        : "r"(a[0]), "r"(a[1]), "r"(a[2]), "r"(a[3]), "r"(b[0]), "r"(b[1]));
}

__device__ __forceinline__ void cp16(void* smem, const void* gmem, int szbytes) {
    uint32_t s = (uint32_t)__cvta_generic_to_shared(smem);
    asm volatile("cp.async.cg.shared.global [%0], [%1], 16, %2;\n"
                 :: "r"(s), "l"(gmem), "r"(szbytes));
}
__device__ __forceinline__ void cp_commit() { asm volatile("cp.async.commit_group;\n"); }
template <int N> __device__ __forceinline__ void cp_wait() {
    asm volatile("cp.async.wait_group %0;\n" :: "n"(N));
}

__device__ __forceinline__ float sigm(float x) { return 1.0f / (1.0f + expf(-x)); }

// accumulator type: fp64 on the recurrent (SPLIT) path to sink accumulation-order noise
template <bool SPLIT> struct AccType { typedef float T; };
template <> struct AccType<true> { typedef double T; };

// ---------------- TF32 GEMM: C[M,N] = concat(A1,A2)[M,K] @ W[K,N] (+bias) ----------------
// Virtual concat A: cols [0,K1) from A1 (row stride lda1), cols [K1,K) from A2 (row stride lda2).
// K1 % 4 == 0, N % 4 == 0, K % 4 == 0, M exact multiple of BM.
// SPLIT=true: 3xTF32 split precision + per-K-block fp32 partials flushed into an fp64
// main accumulator (our per-element noise ~0.3e-6, well under the reference's own fp32 noise).
template <int BM, int BN, int WM_, int WN_, int STAGES, bool SPLIT>
__global__ void __launch_bounds__(WM_ * WN_ * 32)
gemm_tf32_kernel(const float* __restrict__ A1, int lda1, int K1,
                 const float* __restrict__ A2, int lda2,
                 const float* __restrict__ W, const float* __restrict__ bias,
                 float* __restrict__ C, int N, int K) {
    constexpr int BK = 32;
    constexpr int NTH = WM_ * WN_ * 32;
    constexpr int WTM = BM / WM_;
    constexpr int WTN = BN / WN_;
    constexpr int MF = WTM / 16;
    constexpr int NF = WTN / 8;
    constexpr int AST = BK + 4;        // %32==4 -> conflict-free A frag LDS
    constexpr int BST = BN + 8;        // %32==8 -> conflict-free B frag LDS
    typedef typename AccType<SPLIT>::T accT;

    __shared__ float As[STAGES][BM][AST];
    __shared__ float Bs[STAGES][BK][BST];

    const int tid  = threadIdx.x;
    const int wid  = tid >> 5;
    const int lane = tid & 31;
    const int g    = lane >> 2;
    const int tq   = lane & 3;
    const int warp_m = wid % WM_;
    const int warp_n = wid / WM_;
    const int m0 = blockIdx.y * BM;
    const int n0 = blockIdx.x * BN;

    accT acc[MF][NF][4];
#pragma unroll
    for (int mf = 0; mf < MF; ++mf)
#pragma unroll
        for (int nf = 0; nf < NF; ++nf)
#pragma unroll
            for (int r = 0; r < 4; ++r) acc[mf][nf][r] = (accT)0;

    // ---- async tile loader ----
    auto load_tiles = [&](int k0, int s) {
        constexpr int AF4 = BM * BK / 4;
#pragma unroll
        for (int i = 0; i < AF4 / NTH; ++i) {
            int p   = tid + i * NTH;
            int row = p >> 3;
            int kc  = (p & 7) << 2;
            int k   = k0 + kc;
            const float* src = A1;      // valid aligned dummy when sz==0
            int sz = 0;
            if (k < K) {                // k,K both %4 -> full float4 in-bounds
                int gr = m0 + row;
                sz = 16;
                if (k + 4 <= K1) src = A1 + (size_t)gr * lda1 + k;
                else             src = A2 + (size_t)gr * lda2 + (k - K1);
            }
            cp16(&As[s][row][kc], src, sz);
        }
        constexpr int BF4 = BK * BN / 4;
#pragma unroll
        for (int i = 0; i < BF4 / NTH; ++i) {
            int p  = tid + i * NTH;
            int kr = p / (BN / 4);
            int nc = (p % (BN / 4)) << 2;
            int n  = n0 + nc;
            int k  = k0 + kr;
            const float* src = W;
            int sz = 0;
            if (k < K && n < N) { sz = 16; src = W + (size_t)k * N + n; }
            cp16(&Bs[s][kr][nc], src, sz);
        }
    };

    // compute one K-block into a zeroed fp32 partial accumulator, then flush to main acc
    auto compute = [&](int s) {
        float pac[MF][NF][4];
#pragma unroll
        for (int mf = 0; mf < MF; ++mf)
#pragma unroll
            for (int nf = 0; nf < NF; ++nf)
#pragma unroll
                for (int r = 0; r < 4; ++r) pac[mf][nf][r] = 0.0f;

#pragma unroll
        for (int kk = 0; kk < 4; ++kk) {
            uint32_t afh[MF][4], bfh[NF][2];
            uint32_t afl[MF][4], bfl[NF][2];
#pragma unroll
            for (int mf = 0; mf < MF; ++mf) {
                int r = warp_m * WTM + mf * 16;
                float a0 = As[s][r + g][kk * 8 + tq];
                float a1 = As[s][r + g + 8][kk * 8 + tq];
                float a2 = As[s][r + g][kk * 8 + tq + 4];
                float a3 = As[s][r + g + 8][kk * 8 + tq + 4];
                if (SPLIT) {
                    f2tf32_split(a0, afh[mf][0], afl[mf][0]);
                    f2tf32_split(a1, afh[mf][1], afl[mf][1]);
                    f2tf32_split(a2, afh[mf][2], afl[mf][2]);
                    f2tf32_split(a3, afh[mf][3], afl[mf][3]);
                } else {
                    afh[mf][0] = f2tf32(a0); afh[mf][1] = f2tf32(a1);
                    afh[mf][2] = f2tf32(a2); afh[mf][3] = f2tf32(a3);
                }
            }
#pragma unroll
            for (int nf = 0; nf < NF; ++nf) {
                int cn = warp_n * WTN + nf * 8 + g;
                float b0 = Bs[s][kk * 8 + tq][cn];
                float b1 = Bs[s][kk * 8 + tq + 4][cn];
                if (SPLIT) {
                    f2tf32_split(b0, bfh[nf][0], bfl[nf][0]);
                    f2tf32_split(b1, bfh[nf][1], bfl[nf][1]);
                } else {
                    bfh[nf][0] = f2tf32(b0); bfh[nf][1] = f2tf32(b1);
                }
            }
#pragma unroll
            for (int mf = 0; mf < MF; ++mf)
#pragma unroll
                for (int nf = 0; nf < NF; ++nf) {
                    if (SPLIT) {
                        // small cross terms first, then hi*hi
                        mma_tf32(pac[mf][nf], afl[mf], bfh[nf]);
                        mma_tf32(pac[mf][nf], afh[mf], bfl[nf]);
                    }
                    mma_tf32(pac[mf][nf], afh[mf], bfh[nf]);
                }
        }
        // flush block partial into main accumulator (fp64 add on SPLIT path)
#pragma unroll
        for (int mf = 0; mf < MF; ++mf)
#pragma unroll
            for (int nf = 0; nf < NF; ++nf)
#pragma unroll
                for (int r = 0; r < 4; ++r) acc[mf][nf][r] += (accT)pac[mf][nf][r];
    };

    if (STAGES == 2) {
        load_tiles(0, 0);
        cp_commit();
        int buf = 0;
        for (int k0 = 0; k0 < K; k0 += BK) {
            if (k0 + BK < K) load_tiles(k0 + BK, buf ^ 1);
            cp_commit();
            cp_wait<1>();          // current buf's group complete
            __syncthreads();
            compute(buf);
            __syncthreads();
            buf ^= 1;
        }
    } else {
        for (int k0 = 0; k0 < K; k0 += BK) {
            load_tiles(k0, 0);
            cp_commit();
            cp_wait<0>();
            __syncthreads();
            compute(0);
            __syncthreads();
        }
    }

    // ---- store (float2; N even, col-tail checked) ----
#pragma unroll
    for (int mf = 0; mf < MF; ++mf) {
#pragma unroll
        for (int nf = 0; nf < NF; ++nf) {
            int row = m0 + warp_m * WTM + mf * 16 + g;
            int col = n0 + warp_n * WTN + nf * 8 + tq * 2;
            if (col < N) {
                float bx = 0.f, by = 0.f;
                if (bias) { bx = bias[col]; by = bias[col + 1]; }
                float2 v0 = make_float2((float)acc[mf][nf][0] + bx, (float)acc[mf][nf][1] + by);
                float2 v1 = make_float2((float)acc[mf][nf][2] + bx, (float)acc[mf][nf][3] + by);
                *(float2*)(C + (size_t)row * N + col)       = v0;
                *(float2*)(C + (size_t)(row + 8) * N + col) = v1;
            }
        }
    }
}

// ---------------- fused LN4 + gates + LN(c) + zoneout; one CTA per batch row ----------------
// LayerNorm statistics computed in fp64 to eliminate reduction/cancellation noise.
template <int HU>
__global__ void __launch_bounds__(256)
pointwise_kernel(const float* __restrict__ z, const float* __restrict__ bias,
                 const float* __restrict__ gg, const float* __restrict__ bg,
                 const float* __restrict__ gc, const float* __restrict__ bc,
                 float* __restrict__ h, float* __restrict__ c,
                 float* __restrict__ outs /* g_outs + t*HU, or nullptr */) {
    constexpr int NTH = 256;
    __shared__ float sz[4 * HU];
    __shared__ float scp[HU];
    __shared__ double redd[16];
    __shared__ float stat[10];

    const int b = blockIdx.x, tid = threadIdx.x;
    const float* zr = z + (size_t)b * 4 * HU;

    for (int i = tid; i < 4 * HU; i += NTH) sz[i] = zr[i] + bias[i];
    __syncthreads();

    for (int ch = 0; ch < 4; ++ch) {
        double s = 0.0, q = 0.0;
        for (int i = tid; i < HU; i += NTH) {
            double v = (double)sz[ch * HU + i];
            s += v; q += v * v;
        }
#pragma unroll
        for (int o = 16; o; o >>= 1) { s += __shfl_xor_sync(~0u, s, o); q += __shfl_xor_sync(~0u, q, o); }
        if ((tid & 31) == 0) { redd[tid >> 5] = s; redd[8 + (tid >> 5)] = q; }
        __syncthreads();
        if (tid < 32) {
            double ss = (tid < 8) ? redd[tid] : 0.0;
            double qq = (tid < 8) ? redd[8 + tid] : 0.0;
#pragma unroll
            for (int o = 4; o; o >>= 1) { ss += __shfl_xor_sync(~0u, ss, o); qq += __shfl_xor_sync(~0u, qq, o); }
            if (tid == 0) {
                double mu = ss / (double)HU;
                double var = qq / (double)HU - mu * mu;
                stat[ch] = (float)mu;
                stat[4 + ch] = (float)(1.0 / sqrt(var + 1e-5));
            }
        }
        __syncthreads();
    }

    const float mu0 = stat[0], mu1 = stat[1], mu2 = stat[2], mu3 = stat[3];
    const float r0 = stat[4], r1 = stat[5], r2 = stat[6], r3 = stat[7];

    for (int i = tid; i < HU; i += NTH) {
        float iv = (sz[i]          - mu0) * r0 * gg[i]          + bg[i];
        float jv = (sz[HU + i]     - mu1) * r1 * gg[HU + i]     + bg[HU + i];
        float fv = (sz[2 * HU + i] - mu2) * r2 * gg[2 * HU + i] + bg[2 * HU + i];
        float ov = (sz[3 * HU + i] - mu3) * r3 * gg[3 * HU + i] + bg[3 * HU + i];
        float cold = c[(size_t)b * HU + i];
        float cpre = cold * sigm(fv + 1.0f) + sigm(iv) * tanhf(jv);
        scp[i] = cpre;
        sz[3 * HU + i] = ov;
    }
    __syncthreads();

    {
        double s = 0.0, q = 0.0;
        for (int i = tid; i < HU; i += NTH) {
            double v = (double)scp[i];
            s += v; q += v * v;
        }
#pragma unroll
        for (int o = 16; o; o >>= 1) { s += __shfl_xor_sync(~0u, s, o); q += __shfl_xor_sync(~0u, q, o); }
        if ((tid & 31) == 0) { redd[tid >> 5] = s; redd[8 + (tid >> 5)] = q; }
        __syncthreads();
        if (tid < 32) {
            double ss = (tid < 8) ? redd[tid] : 0.0;
            double qq = (tid < 8) ? redd[8 + tid] : 0.0;
#pragma unroll
            for (int o = 4; o; o >>= 1) { ss += __shfl_xor_sync(~0u, ss, o); qq += __shfl_xor_sync(~0u, qq, o); }
            if (tid == 0) {
                double mu = ss / (double)HU;
                double var = qq / (double)HU - mu * mu;
                stat[8] = (float)mu;
                stat[9] = (float)(1.0 / sqrt(var + 1e-5));
            }
        }
        __syncthreads();
    }
    const float muc = stat[8], rc = stat[9];

    for (int i = tid; i < HU; i += NTH) {
        float cpre = scp[i];
        float nh = tanhf((cpre - muc) * rc * gc[i] + bc[i]) * sigm(sz[3 * HU + i]);
        float hold = h[(size_t)b * HU + i];
        float cold = c[(size_t)b * HU + i];
        float hn = 0.9f * nh + 0.1f * hold;
        float cn = 0.5f * cpre + 0.5f * cold;
        h[(size_t)b * HU + i] = hn;
        c[(size_t)b * HU + i] = cn;
        if (outs) outs[(size_t)b * T_ * HU + i] = hn;
    }
}

// ---------------- init & epilogue ----------------
__global__ void zero_states_kernel() {
    int i = blockIdx.x * blockDim.x + threadIdx.x;
    if (i < B_ * F_) { g_fh[i] = 0.f; g_fc[i] = 0.f; }
    if (i < B_ * S_) { g_sh[i] = 0.f; g_sc[i] = 0.f; }
}

__global__ void copy_states_kernel(float* __restrict__ out) {
    int i = blockIdx.x * blockDim.x + threadIdx.x;
    const int NF = B_ * F_;
    const int NS = B_ * S_;
    if (i < NF)                       out[i] = g_fh[i];
    else if (i < 2 * NF)              out[i] = g_fc[i - NF];
    else if (i < 2 * NF + NS)         out[i] = g_sh[i - 2 * NF];
    else if (i < 2 * NF + 2 * NS)     out[i] = g_sc[i - 2 * NF - NS];
}

// ---------------- launch ----------------
extern "C" void kernel_launch(void* const* d_in, const int* in_sizes, int n_in,
                              void* d_out, int out_size) {
    const float* inputs = (const float*)d_in[0];
    const float* W0  = (const float*)d_in[1];
    const float* b0  = (const float*)d_in[2];
    const float* g0  = (const float*)d_in[3];
    const float* bg0 = (const float*)d_in[4];
    const float* gc0 = (const float*)d_in[5];
    const float* bc0 = (const float*)d_in[6];
    const float* W1  = (const float*)d_in[7];
    const float* b1  = (const float*)d_in[8];
    const float* g1  = (const float*)d_in[9];
    const float* bg1 = (const float*)d_in[10];
    const float* gc1 = (const float*)d_in[11];
    const float* bc1 = (const float*)d_in[12];
    const float* WS  = (const float*)d_in[13];
    const float* bS  = (const float*)d_in[14];
    const float* gS  = (const float*)d_in[15];
    const float* bgS = (const float*)d_in[16];
    const float* gcS = (const float*)d_in[17];
    const float* bcS = (const float*)d_in[18];
    const float* Wout = (const float*)d_in[19];
    const float* bout = (const float*)d_in[20];
    float* out = (float*)d_out;

    float *fh, *fc, *sh, *sc, *z, *outs;
    cudaGetSymbolAddress((void**)&fh, g_fh);
    cudaGetSymbolAddress((void**)&fc, g_fc);
    cudaGetSymbolAddress((void**)&sh, g_sh);
    cudaGetSymbolAddress((void**)&sc, g_sc);
    cudaGetSymbolAddress((void**)&z, g_z);
    cudaGetSymbolAddress((void**)&outs, g_outs);

    zero_states_kernel<<<350, 256>>>();

    for (int t = 0; t < T_; ++t) {
        // Fast cell 0: concat(x_t[128], fh[700]) @ W0 -> z[128,2800]   (3xTF32 + fp64 acc)
        gemm_tf32_kernel<64, 32, 2, 2, 2, true><<<dim3(88, 2), 128>>>(
            inputs + (size_t)t * E_, T_ * E_, E_, fh, F_, W0, nullptr, z, 4 * F_, E_ + F_);
        pointwise_kernel<F_><<<B_, 256>>>(z, b0, g0, bg0, gc0, bc0, fh, fc, nullptr);

        // Slow cell: concat(fh[700], sh[400]) @ WS -> z[128,1600]      (3xTF32 + fp64 acc)
        gemm_tf32_kernel<64, 32, 2, 2, 2, true><<<dim3(50, 2), 128>>>(
            fh, F_, F_, sh, S_, WS, nullptr, z, 4 * S_, F_ + S_);
        pointwise_kernel<S_><<<B_, 256>>>(z, bS, gS, bgS, gcS, bcS, sh, sc, nullptr);

        // Fast cell 1: concat(sh[400], fh[700]) @ W1 -> z[128,2800]    (3xTF32 + fp64 acc)
        gemm_tf32_kernel<64, 32, 2, 2, 2, true><<<dim3(88, 2), 128>>>(
            sh, S_, S_, fh, F_, W1, nullptr, z, 4 * F_, S_ + F_);
        pointwise_kernel<F_><<<B_, 256>>>(z, b1, g1, bg1, gc1, bc1, fh, fc, outs + (size_t)t * F_);
    }

    // Output projection: g_outs[12800,700] @ Wout[700,10000] + bout -> logits (single TF32)
    gemm_tf32_kernel<128, 128, 2, 4, 1, false><<<dim3(79, 100), 256>>>(
        outs, F_, F_, outs, F_, Wout, bout, out, V_, F_);

    // Final states appended after logits
    copy_states_kernel<<<1100, 256>>>(out + (size_t)B_ * T_ * V_);
}

// round 9
// speedup vs baseline: 1.5093x; 1.5093x over previous
#include <cuda_runtime.h>
#include <cstdint>
#include <math.h>

#define B_ 128
#define T_ 100
#define E_ 128
#define F_ 700
#define S_ 400
#define V_ 10000

// ---------------- static device scratch (no allocations allowed) ----------------
static __device__ __align__(16) float g_fh[B_ * F_];
static __device__ __align__(16) float g_fc[B_ * F_];
static __device__ __align__(16) float g_sh[B_ * S_];
static __device__ __align__(16) float g_sc[B_ * S_];
// split-K partial planes: max(3 * 128*2800, 4 * 128*1600) = 1,075,200 floats (4.3 MB)
static __device__ __align__(16) float g_z[3 * B_ * 4 * F_];
static __device__ __align__(16) float g_outs[B_ * T_ * F_];      // fh outputs, row = b*T + t  (35.8 MB)

// ---------------- helpers ----------------
__device__ __forceinline__ uint32_t f2tf32(float x) {
    uint32_t r;
    asm("cvt.rna.tf32.f32 %0, %1;" : "=r"(r) : "f"(x));
    return r;
}

// split x into hi (tf32) + lo (tf32 of residual): 3xTF32 emulation of fp32
__device__ __forceinline__ void f2tf32_split(float x, uint32_t& hi, uint32_t& lo) {
    hi = f2tf32(x);
    lo = f2tf32(x - __uint_as_float(hi));
}

__device__ __forceinline__ void mma_tf32(float* d, const uint32_t* a, const uint32_t* b) {
    asm volatile(
        "mma.sync.aligned.m16n8k8.row.col.f32.tf32.tf32.f32 "
        "{%0,%1,%2,%3}, {%4,%5,%6,%7}, {%8,%9}, {%0,%1,%2,%3};\n"
        : "+f"(d[0]), "+f"(d[1]), "+f"(d[2]), "+f"(d[3])
        : "r"(a[0]), "r"(a[1]), "r"(a[2]), "r"(a[3]), "r"(b[0]), "r"(b[1]));
}

__device__ __forceinline__ void cp16(void* smem, const void* gmem, int szbytes) {
    uint32_t s = (uint32_t)__cvta_generic_to_shared(smem);
    asm volatile("cp.async.cg.shared.global [%0], [%1], 16, %2;\n"
                 :: "r"(s), "l"(gmem), "r"(szbytes));
}
__device__ __forceinline__ void cp_commit() { asm volatile("cp.async.commit_group;\n"); }
template <int N> __device__ __forceinline__ void cp_wait() {
    asm volatile("cp.async.wait_group %0;\n" :: "n"(N));
}

__device__ __forceinline__ float sigm(float x) { return 1.0f / (1.0f + expf(-x)); }

// accumulator type: fp64 on the recurrent (SPLIT) path to sink accumulation-order noise
template <bool SPLIT> struct AccType { typedef float T; };
template <> struct AccType<true> { typedef double T; };

// ---------------- TF32 GEMM: C[M,N] = concat(A1,A2)[M,K] @ W[K,N] (+bias) ----------------
// Virtual concat A: cols [0,K1) from A1 (row stride lda1), cols [K1,K) from A2 (row stride lda2).
// K1 % 4 == 0, N % 4 == 0, M exact multiple of BM.
// SPLIT=true: 3xTF32 split precision + per-K-block fp32 partials flushed into an fp64
// main accumulator.
// NSPLIT>1: split-K — blockIdx.z covers K-range [kBegin,kEnd) on BK boundaries, writing a
// partial plane at C + z*pstride. Consumer sums planes in fixed order (deterministic).
template <int BM, int BN, int WM_, int WN_, int STAGES, bool SPLIT, int NSPLIT>
__global__ void __launch_bounds__(WM_ * WN_ * 32)
gemm_tf32_kernel(const float* __restrict__ A1, int lda1, int K1,
                 const float* __restrict__ A2, int lda2,
                 const float* __restrict__ W, const float* __restrict__ bias,
                 float* __restrict__ C, int N, int K, size_t pstride) {
    constexpr int BK = 32;
    constexpr int NTH = WM_ * WN_ * 32;
    constexpr int WTM = BM / WM_;
    constexpr int WTN = BN / WN_;
    constexpr int MF = WTM / 16;
    constexpr int NF = WTN / 8;
    constexpr int AST = BK + 4;        // %32==4 -> conflict-free A frag LDS
    constexpr int BST = BN + 8;        // %32==8 -> conflict-free B frag LDS
    typedef typename AccType<SPLIT>::T accT;

    __shared__ float As[STAGES][BM][AST];
    __shared__ float Bs[STAGES][BK][BST];

    const int tid  = threadIdx.x;
    const int wid  = tid >> 5;
    const int lane = tid & 31;
    const int g    = lane >> 2;
    const int tq   = lane & 3;
    const int warp_m = wid % WM_;
    const int warp_n = wid / WM_;
    const int m0 = blockIdx.y * BM;
    const int n0 = blockIdx.x * BN;

    // ---- split-K range (BK-aligned; last split takes the K tail) ----
    const int nblk = (K + BK - 1) / BK;
    const int zb = (NSPLIT > 1) ? blockIdx.z : 0;
    const int kBegin = ((zb * nblk) / NSPLIT) * BK;
    const int kEnd   = (zb == NSPLIT - 1) ? K : (((zb + 1) * nblk) / NSPLIT) * BK;
    float* Cz = C + (size_t)zb * pstride;

    accT acc[MF][NF][4];
#pragma unroll
    for (int mf = 0; mf < MF; ++mf)
#pragma unroll
        for (int nf = 0; nf < NF; ++nf)
#pragma unroll
            for (int r = 0; r < 4; ++r) acc[mf][nf][r] = (accT)0;

    // ---- async tile loader ----
    auto load_tiles = [&](int k0, int s) {
        constexpr int AF4 = BM * BK / 4;
#pragma unroll
        for (int i = 0; i < AF4 / NTH; ++i) {
            int p   = tid + i * NTH;
            int row = p >> 3;
            int kc  = (p & 7) << 2;
            int k   = k0 + kc;
            const float* src = A1;      // valid aligned dummy when sz==0
            int sz = 0;
            if (k < K) {                // k,K1 %4 -> float4 never straddles
                int gr = m0 + row;
                sz = 16;
                if (k + 4 <= K1) src = A1 + (size_t)gr * lda1 + k;
                else             src = A2 + (size_t)gr * lda2 + (k - K1);
            }
            cp16(&As[s][row][kc], src, sz);
        }
        constexpr int BF4 = BK * BN / 4;
#pragma unroll
        for (int i = 0; i < BF4 / NTH; ++i) {
            int p  = tid + i * NTH;
            int kr = p / (BN / 4);
            int nc = (p % (BN / 4)) << 2;
            int n  = n0 + nc;
            int k  = k0 + kr;
            const float* src = W;
            int sz = 0;
            if (k < K && n < N) { sz = 16; src = W + (size_t)k * N + n; }
            cp16(&Bs[s][kr][nc], src, sz);
        }
    };

    // compute one K-block into a zeroed fp32 partial accumulator, then flush to main acc
    auto compute = [&](int s) {
        float pac[MF][NF][4];
#pragma unroll
        for (int mf = 0; mf < MF; ++mf)
#pragma unroll
            for (int nf = 0; nf < NF; ++nf)
#pragma unroll
                for (int r = 0; r < 4; ++r) pac[mf][nf][r] = 0.0f;

#pragma unroll
        for (int kk = 0; kk < 4; ++kk) {
            uint32_t afh[MF][4], bfh[NF][2];
            uint32_t afl[MF][4], bfl[NF][2];
#pragma unroll
            for (int mf = 0; mf < MF; ++mf) {
                int r = warp_m * WTM + mf * 16;
                float a0 = As[s][r + g][kk * 8 + tq];
                float a1 = As[s][r + g + 8][kk * 8 + tq];
                float a2 = As[s][r + g][kk * 8 + tq + 4];
                float a3 = As[s][r + g + 8][kk * 8 + tq + 4];
                if (SPLIT) {
                    f2tf32_split(a0, afh[mf][0], afl[mf][0]);
                    f2tf32_split(a1, afh[mf][1], afl[mf][1]);
                    f2tf32_split(a2, afh[mf][2], afl[mf][2]);
                    f2tf32_split(a3, afh[mf][3], afl[mf][3]);
                } else {
                    afh[mf][0] = f2tf32(a0); afh[mf][1] = f2tf32(a1);
                    afh[mf][2] = f2tf32(a2); afh[mf][3] = f2tf32(a3);
                }
            }
#pragma unroll
            for (int nf = 0; nf < NF; ++nf) {
                int cn = warp_n * WTN + nf * 8 + g;
                float b0 = Bs[s][kk * 8 + tq][cn];
                float b1 = Bs[s][kk * 8 + tq + 4][cn];
                if (SPLIT) {
                    f2tf32_split(b0, bfh[nf][0], bfl[nf][0]);
                    f2tf32_split(b1, bfh[nf][1], bfl[nf][1]);
                } else {
                    bfh[nf][0] = f2tf32(b0); bfh[nf][1] = f2tf32(b1);
                }
            }
#pragma unroll
            for (int mf = 0; mf < MF; ++mf)
#pragma unroll
                for (int nf = 0; nf < NF; ++nf) {
                    if (SPLIT) {
                        // small cross terms first, then hi*hi
                        mma_tf32(pac[mf][nf], afl[mf], bfh[nf]);
                        mma_tf32(pac[mf][nf], afh[mf], bfl[nf]);
                    }
                    mma_tf32(pac[mf][nf], afh[mf], bfh[nf]);
                }
        }
        // flush block partial into main accumulator (fp64 add on SPLIT path)
#pragma unroll
        for (int mf = 0; mf < MF; ++mf)
#pragma unroll
            for (int nf = 0; nf < NF; ++nf)
#pragma unroll
                for (int r = 0; r < 4; ++r) acc[mf][nf][r] += (accT)pac[mf][nf][r];
    };

    if (STAGES == 2) {
        load_tiles(kBegin, 0);
        cp_commit();
        int buf = 0;
        for (int k0 = kBegin; k0 < kEnd; k0 += BK) {
            if (k0 + BK < kEnd) load_tiles(k0 + BK, buf ^ 1);
            cp_commit();
            cp_wait<1>();          // current buf's group complete
            __syncthreads();
            compute(buf);
            __syncthreads();
            buf ^= 1;
        }
    } else {
        for (int k0 = kBegin; k0 < kEnd; k0 += BK) {
            load_tiles(k0, 0);
            cp_commit();
            cp_wait<0>();
            __syncthreads();
            compute(0);
            __syncthreads();
        }
    }

    // ---- store (float2; N even, col-tail checked) ----
#pragma unroll
    for (int mf = 0; mf < MF; ++mf) {
#pragma unroll
        for (int nf = 0; nf < NF; ++nf) {
            int row = m0 + warp_m * WTM + mf * 16 + g;
            int col = n0 + warp_n * WTN + nf * 8 + tq * 2;
            if (col < N) {
                float bx = 0.f, by = 0.f;
                if (bias) { bx = bias[col]; by = bias[col + 1]; }
                float2 v0 = make_float2((float)acc[mf][nf][0] + bx, (float)acc[mf][nf][1] + by);
                float2 v1 = make_float2((float)acc[mf][nf][2] + bx, (float)acc[mf][nf][3] + by);
                *(float2*)(Cz + (size_t)row * N + col)       = v0;
                *(float2*)(Cz + (size_t)(row + 8) * N + col) = v1;
            }
        }
    }
}

// ---------------- fused split-K reduce + LN4 + gates + LN(c) + zoneout ----------------
// One CTA per batch row. Sums NS split-K partial planes in fixed order (deterministic),
// LayerNorm statistics in fp64.
template <int HU, int NS>
__global__ void __launch_bounds__(256)
pointwise_kernel(const float* __restrict__ z, size_t pstride,
                 const float* __restrict__ bias,
                 const float* __restrict__ gg, const float* __restrict__ bg,
                 const float* __restrict__ gc, const float* __restrict__ bc,
                 float* __restrict__ h, float* __restrict__ c,
                 float* __restrict__ outs /* g_outs + t*HU, or nullptr */) {
    constexpr int NTH = 256;
    __shared__ float sz[4 * HU];
    __shared__ float scp[HU];
    __shared__ double redd[16];
    __shared__ float stat[10];

    const int b = blockIdx.x, tid = threadIdx.x;
    const float* zr = z + (size_t)b * 4 * HU;

    for (int i = tid; i < 4 * HU; i += NTH) {
        float v = zr[i];
#pragma unroll
        for (int s = 1; s < NS; ++s) v += zr[s * pstride + i];
        sz[i] = v + bias[i];
    }
    __syncthreads();

    for (int ch = 0; ch < 4; ++ch) {
        double s = 0.0, q = 0.0;
        for (int i = tid; i < HU; i += NTH) {
            double v = (double)sz[ch * HU + i];
            s += v; q += v * v;
        }
#pragma unroll
        for (int o = 16; o; o >>= 1) { s += __shfl_xor_sync(~0u, s, o); q += __shfl_xor_sync(~0u, q, o); }
        if ((tid & 31) == 0) { redd[tid >> 5] = s; redd[8 + (tid >> 5)] = q; }
        __syncthreads();
        if (tid < 32) {
            double ss = (tid < 8) ? redd[tid] : 0.0;
            double qq = (tid < 8) ? redd[8 + tid] : 0.0;
#pragma unroll
            for (int o = 4; o; o >>= 1) { ss += __shfl_xor_sync(~0u, ss, o); qq += __shfl_xor_sync(~0u, qq, o); }
            if (tid == 0) {
                double mu = ss / (double)HU;
                double var = qq / (double)HU - mu * mu;
                stat[ch] = (float)mu;
                stat[4 + ch] = (float)(1.0 / sqrt(var + 1e-5));
            }
        }
        __syncthreads();
    }

    const float mu0 = stat[0], mu1 = stat[1], mu2 = stat[2], mu3 = stat[3];
    const float r0 = stat[4], r1 = stat[5], r2 = stat[6], r3 = stat[7];

    for (int i = tid; i < HU; i += NTH) {
        float iv = (sz[i]          - mu0) * r0 * gg[i]          + bg[i];
        float jv = (sz[HU + i]     - mu1) * r1 * gg[HU + i]     + bg[HU + i];
        float fv = (sz[2 * HU + i] - mu2) * r2 * gg[2 * HU + i] + bg[2 * HU + i];
        float ov = (sz[3 * HU + i] - mu3) * r3 * gg[3 * HU + i] + bg[3 * HU + i];
        float cold = c[(size_t)b * HU + i];
        float cpre = cold * sigm(fv + 1.0f) + sigm(iv) * tanhf(jv);
        scp[i] = cpre;
        sz[3 * HU + i] = ov;
    }
    __syncthreads();

    {
        double s = 0.0, q = 0.0;
        for (int i = tid; i < HU; i += NTH) {
            double v = (double)scp[i];
            s += v; q += v * v;
        }
#pragma unroll
        for (int o = 16; o; o >>= 1) { s += __shfl_xor_sync(~0u, s, o); q += __shfl_xor_sync(~0u, q, o); }
        if ((tid & 31) == 0) { redd[tid >> 5] = s; redd[8 + (tid >> 5)] = q; }
        __syncthreads();
        if (tid < 32) {
            double ss = (tid < 8) ? redd[tid] : 0.0;
            double qq = (tid < 8) ? redd[8 + tid] : 0.0;
#pragma unroll
            for (int o = 4; o; o >>= 1) { ss += __shfl_xor_sync(~0u, ss, o); qq += __shfl_xor_sync(~0u, qq, o); }
            if (tid == 0) {
                double mu = ss / (double)HU;
                double var = qq / (double)HU - mu * mu;
                stat[8] = (float)mu;
                stat[9] = (float)(1.0 / sqrt(var + 1e-5));
            }
        }
        __syncthreads();
    }
    const float muc = stat[8], rc = stat[9];

    for (int i = tid; i < HU; i += NTH) {
        float cpre = scp[i];
        float nh = tanhf((cpre - muc) * rc * gc[i] + bc[i]) * sigm(sz[3 * HU + i]);
        float hold = h[(size_t)b * HU + i];
        float cold = c[(size_t)b * HU + i];
        float hn = 0.9f * nh + 0.1f * hold;
        float cn = 0.5f * cpre + 0.5f * cold;
        h[(size_t)b * HU + i] = hn;
        c[(size_t)b * HU + i] = cn;
        if (outs) outs[(size_t)b * T_ * HU + i] = hn;
    }
}

// ---------------- init & epilogue ----------------
__global__ void zero_states_kernel() {
    int i = blockIdx.x * blockDim.x + threadIdx.x;
    if (i < B_ * F_) { g_fh[i] = 0.f; g_fc[i] = 0.f; }
    if (i < B_ * S_) { g_sh[i] = 0.f; g_sc[i] = 0.f; }
}

__global__ void copy_states_kernel(float* __restrict__ out) {
    int i = blockIdx.x * blockDim.x + threadIdx.x;
    const int NF = B_ * F_;
    const int NS = B_ * S_;
    if (i < NF)                       out[i] = g_fh[i];
    else if (i < 2 * NF)              out[i] = g_fc[i - NF];
    else if (i < 2 * NF + NS)         out[i] = g_sh[i - 2 * NF];
    else if (i < 2 * NF + 2 * NS)     out[i] = g_sc[i - 2 * NF - NS];
}

// ---------------- launch ----------------
extern "C" void kernel_launch(void* const* d_in, const int* in_sizes, int n_in,
                              void* d_out, int out_size) {
    const float* inputs = (const float*)d_in[0];
    const float* W0  = (const float*)d_in[1];
    const float* b0  = (const float*)d_in[2];
    const float* g0  = (const float*)d_in[3];
    const float* bg0 = (const float*)d_in[4];
    const float* gc0 = (const float*)d_in[5];
    const float* bc0 = (const float*)d_in[6];
    const float* W1  = (const float*)d_in[7];
    const float* b1  = (const float*)d_in[8];
    const float* g1  = (const float*)d_in[9];
    const float* bg1 = (const float*)d_in[10];
    const float* gc1 = (const float*)d_in[11];
    const float* bc1 = (const float*)d_in[12];
    const float* WS  = (const float*)d_in[13];
    const float* bS  = (const float*)d_in[14];
    const float* gS  = (const float*)d_in[15];
    const float* bgS = (const float*)d_in[16];
    const float* gcS = (const float*)d_in[17];
    const float* bcS = (const float*)d_in[18];
    const float* Wout = (const float*)d_in[19];
    const float* bout = (const float*)d_in[20];
    float* out = (float*)d_out;

    float *fh, *fc, *sh, *sc, *z, *outs;
    cudaGetSymbolAddress((void**)&fh, g_fh);
    cudaGetSymbolAddress((void**)&fc, g_fc);
    cudaGetSymbolAddress((void**)&sh, g_sh);
    cudaGetSymbolAddress((void**)&sc, g_sc);
    cudaGetSymbolAddress((void**)&z, g_z);
    cudaGetSymbolAddress((void**)&outs, g_outs);

    const size_t psF = (size_t)B_ * 4 * F_;   // fast-cell partial plane stride
    const size_t psS = (size_t)B_ * 4 * S_;   // slow-cell partial plane stride

    zero_states_kernel<<<350, 256>>>();

    for (int t = 0; t < T_; ++t) {
        // Fast cell 0: concat(x_t[128], fh[700]) @ W0 -> 3 partial planes
        gemm_tf32_kernel<64, 32, 2, 2, 2, true, 3><<<dim3(88, 2, 3), 128>>>(
            inputs + (size_t)t * E_, T_ * E_, E_, fh, F_, W0, nullptr, z, 4 * F_, E_ + F_, psF);
        pointwise_kernel<F_, 3><<<B_, 256>>>(z, psF, b0, g0, bg0, gc0, bc0, fh, fc, nullptr);

        // Slow cell: concat(fh[700], sh[400]) @ WS -> 4 partial planes
        gemm_tf32_kernel<64, 32, 2, 2, 2, true, 4><<<dim3(50, 2, 4), 128>>>(
            fh, F_, F_, sh, S_, WS, nullptr, z, 4 * S_, F_ + S_, psS);
        pointwise_kernel<S_, 4><<<B_, 256>>>(z, psS, bS, gS, bgS, gcS, bcS, sh, sc, nullptr);

        // Fast cell 1: concat(sh[400], fh[700]) @ W1 -> 3 partial planes
        gemm_tf32_kernel<64, 32, 2, 2, 2, true, 3><<<dim3(88, 2, 3), 128>>>(
            sh, S_, S_, fh, F_, W1, nullptr, z, 4 * F_, S_ + F_, psF);
        pointwise_kernel<F_, 3><<<B_, 256>>>(z, psF, b1, g1, bg1, gc1, bc1, fh, fc,
                                             outs + (size_t)t * F_);
    }

    // Output projection: g_outs[12800,700] @ Wout[700,10000] + bout -> logits (single TF32)
    gemm_tf32_kernel<128, 128, 2, 4, 1, false, 1><<<dim3(79, 100, 1), 256>>>(
        outs, F_, F_, outs, F_, Wout, bout, out, V_, F_, 0);

    // Final states appended after logits
    copy_states_kernel<<<1100, 256>>>(out + (size_t)B_ * T_ * V_);
}

// round 13
// speedup vs baseline: 1.5765x; 1.0445x over previous
#include <cuda_runtime.h>
#include <cstdint>
#include <math.h>

#define B_ 128
#define T_ 100
#define E_ 128
#define F_ 700
#define S_ 400
#define V_ 10000

// ---------------- static device scratch (no allocations allowed) ----------------
static __device__ __align__(16) float g_fh[B_ * F_];
static __device__ __align__(16) float g_fc[B_ * F_];
static __device__ __align__(16) float g_sh[B_ * S_];
static __device__ __align__(16) float g_sc[B_ * S_];
// split-K partial planes: fast 4 * 128*2800 = slow 7 * 128*1600 = 1,433,600 floats (5.7 MB)
static __device__ __align__(16) float g_z[4 * B_ * 4 * F_];
static __device__ __align__(16) float g_outs[B_ * T_ * F_];      // fh outputs, row = b*T + t  (35.8 MB)

// ---------------- helpers ----------------
__device__ __forceinline__ uint32_t f2tf32(float x) {
    uint32_t r;
    asm("cvt.rna.tf32.f32 %0, %1;" : "=r"(r) : "f"(x));
    return r;
}

// split x into hi (tf32) + lo (tf32 of residual): 3xTF32 emulation of fp32
__device__ __forceinline__ void f2tf32_split(float x, uint32_t& hi, uint32_t& lo) {
    hi = f2tf32(x);
    lo = f2tf32(x - __uint_as_float(hi));
}

__device__ __forceinline__ void mma_tf32(float* d, const uint32_t* a, const uint32_t* b) {
    asm volatile(
        "mma.sync.aligned.m16n8k8.row.col.f32.tf32.tf32.f32 "
        "{%0,%1,%2,%3}, {%4,%5,%6,%7}, {%8,%9}, {%0,%1,%2,%3};\n"
        : "+f"(d[0]), "+f"(d[1]), "+f"(d[2]), "+f"(d[3])
        : "r"(a[0]), "r"(a[1]), "r"(a[2]), "r"(a[3]), "r"(b[0]), "r"(b[1]));
}

__device__ __forceinline__ void cp16(void* smem, const void* gmem, int szbytes) {
    uint32_t s = (uint32_t)__cvta_generic_to_shared(smem);
    asm volatile("cp.async.cg.shared.global [%0], [%1], 16, %2;\n"
                 :: "r"(s), "l"(gmem), "r"(szbytes));
}
__device__ __forceinline__ void cp_commit() { asm volatile("cp.async.commit_group;\n"); }
template <int N> __device__ __forceinline__ void cp_wait() {
    asm volatile("cp.async.wait_group %0;\n" :: "n"(N));
}

__device__ __forceinline__ float sigm(float x) { return 1.0f / (1.0f + expf(-x)); }

// accumulator type: fp64 on the recurrent (SPLIT) path to sink accumulation-order noise
template <bool SPLIT> struct AccType { typedef float T; };
template <> struct AccType<true> { typedef double T; };

// ---------------- TF32 GEMM: C[M,N] = concat(A1,A2)[M,K] @ W[K,N] (+bias) ----------------
// Virtual concat A: cols [0,K1) from A1 (row stride lda1), cols [K1,K) from A2 (row stride lda2).
// K1 % 4 == 0, N % 4 == 0, M exact multiple of BM.
// SPLIT=true: 3xTF32 split precision + per-K-block fp32 partials flushed into an fp64
// main accumulator.
// NSPLIT>1: split-K — blockIdx.z covers K-range [kBegin,kEnd) on BK boundaries, writing a
// partial plane at C + z*pstride. Consumer sums planes in fixed order (deterministic).
// MINCTA: minBlocksPerMultiprocessor hint to hold registers under the occupancy cap.
template <int BM, int BN, int WM_, int WN_, int STAGES, bool SPLIT, int NSPLIT, int MINCTA>
__global__ void __launch_bounds__(WM_ * WN_ * 32, MINCTA)
gemm_tf32_kernel(const float* __restrict__ A1, int lda1, int K1,
                 const float* __restrict__ A2, int lda2,
                 const float* __restrict__ W, const float* __restrict__ bias,
                 float* __restrict__ C, int N, int K, size_t pstride) {
    constexpr int BK = 32;
    constexpr int NTH = WM_ * WN_ * 32;
    constexpr int WTM = BM / WM_;
    constexpr int WTN = BN / WN_;
    constexpr int MF = WTM / 16;
    constexpr int NF = WTN / 8;
    constexpr int AST = BK + 4;        // %32==4 -> conflict-free A frag LDS
    constexpr int BST = BN + 8;        // %32==8 -> conflict-free B frag LDS
    typedef typename AccType<SPLIT>::T accT;

    __shared__ float As[STAGES][BM][AST];
    __shared__ float Bs[STAGES][BK][BST];

    const int tid  = threadIdx.x;
    const int wid  = tid >> 5;
    const int lane = tid & 31;
    const int g    = lane >> 2;
    const int tq   = lane & 3;
    const int warp_m = wid % WM_;
    const int warp_n = wid / WM_;
    const int m0 = blockIdx.y * BM;
    const int n0 = blockIdx.x * BN;

    // ---- split-K range (BK-aligned; last split takes the K tail) ----
    const int nblk = (K + BK - 1) / BK;
    const int zb = (NSPLIT > 1) ? blockIdx.z : 0;
    const int kBegin = ((zb * nblk) / NSPLIT) * BK;
    const int kEnd   = (zb == NSPLIT - 1) ? K : (((zb + 1) * nblk) / NSPLIT) * BK;
    float* Cz = C + (size_t)zb * pstride;

    accT acc[MF][NF][4];
#pragma unroll
    for (int mf = 0; mf < MF; ++mf)
#pragma unroll
        for (int nf = 0; nf < NF; ++nf)
#pragma unroll
            for (int r = 0; r < 4; ++r) acc[mf][nf][r] = (accT)0;

    // ---- async tile loader ----
    auto load_tiles = [&](int k0, int s) {
        constexpr int AF4 = BM * BK / 4;
#pragma unroll
        for (int i = 0; i < AF4 / NTH; ++i) {
            int p   = tid + i * NTH;
            int row = p >> 3;
            int kc  = (p & 7) << 2;
            int k   = k0 + kc;
            const float* src = A1;      // valid aligned dummy when sz==0
            int sz = 0;
            if (k < K) {                // k,K1 %4 -> float4 never straddles
                int gr = m0 + row;
                sz = 16;
                if (k + 4 <= K1) src = A1 + (size_t)gr * lda1 + k;
                else             src = A2 + (size_t)gr * lda2 + (k - K1);
            }
            cp16(&As[s][row][kc], src, sz);
        }
        constexpr int BF4 = BK * BN / 4;
#pragma unroll
        for (int i = 0; i < BF4 / NTH; ++i) {
            int p  = tid + i * NTH;
            int kr = p / (BN / 4);
            int nc = (p % (BN / 4)) << 2;
            int n  = n0 + nc;
            int k  = k0 + kr;
            const float* src = W;
            int sz = 0;
            if (k < K && n < N) { sz = 16; src = W + (size_t)k * N + n; }
            cp16(&Bs[s][kr][nc], src, sz);
        }
    };

    // compute one K-block into a zeroed fp32 partial accumulator, then flush to main acc
    auto compute = [&](int s) {
        float pac[MF][NF][4];
#pragma unroll
        for (int mf = 0; mf < MF; ++mf)
#pragma unroll
            for (int nf = 0; nf < NF; ++nf)
#pragma unroll
                for (int r = 0; r < 4; ++r) pac[mf][nf][r] = 0.0f;

#pragma unroll
        for (int kk = 0; kk < 4; ++kk) {
            uint32_t afh[MF][4], bfh[NF][2];
            uint32_t afl[MF][4], bfl[NF][2];
#pragma unroll
            for (int mf = 0; mf < MF; ++mf) {
                int r = warp_m * WTM + mf * 16;
                float a0 = As[s][r + g][kk * 8 + tq];
                float a1 = As[s][r + g + 8][kk * 8 + tq];
                float a2 = As[s][r + g][kk * 8 + tq + 4];
                float a3 = As[s][r + g + 8][kk * 8 + tq + 4];
                if (SPLIT) {
                    f2tf32_split(a0, afh[mf][0], afl[mf][0]);
                    f2tf32_split(a1, afh[mf][1], afl[mf][1]);
                    f2tf32_split(a2, afh[mf][2], afl[mf][2]);
                    f2tf32_split(a3, afh[mf][3], afl[mf][3]);
                } else {
                    afh[mf][0] = f2tf32(a0); afh[mf][1] = f2tf32(a1);
                    afh[mf][2] = f2tf32(a2); afh[mf][3] = f2tf32(a3);
                }
            }
#pragma unroll
            for (int nf = 0; nf < NF; ++nf) {
                int cn = warp_n * WTN + nf * 8 + g;
                float b0 = Bs[s][kk * 8 + tq][cn];
                float b1 = Bs[s][kk * 8 + tq + 4][cn];
                if (SPLIT) {
                    f2tf32_split(b0, bfh[nf][0], bfl[nf][0]);
                    f2tf32_split(b1, bfh[nf][1], bfl[nf][1]);
                } else {
                    bfh[nf][0] = f2tf32(b0); bfh[nf][1] = f2tf32(b1);
                }
            }
#pragma unroll
            for (int mf = 0; mf < MF; ++mf)
#pragma unroll
                for (int nf = 0; nf < NF; ++nf) {
                    if (SPLIT) {
                        // small cross terms first, then hi*hi
                        mma_tf32(pac[mf][nf], afl[mf], bfh[nf]);
                        mma_tf32(pac[mf][nf], afh[mf], bfl[nf]);
                    }
                    mma_tf32(pac[mf][nf], afh[mf], bfh[nf]);
                }
        }
        // flush block partial into main accumulator (fp64 add on SPLIT path)
#pragma unroll
        for (int mf = 0; mf < MF; ++mf)
#pragma unroll
            for (int nf = 0; nf < NF; ++nf)
#pragma unroll
                for (int r = 0; r < 4; ++r) acc[mf][nf][r] += (accT)pac[mf][nf][r];
    };

    if (STAGES == 2) {
        load_tiles(kBegin, 0);
        cp_commit();
        int buf = 0;
        for (int k0 = kBegin; k0 < kEnd; k0 += BK) {
            if (k0 + BK < kEnd) load_tiles(k0 + BK, buf ^ 1);
            cp_commit();
            cp_wait<1>();          // current buf's group complete
            __syncthreads();
            compute(buf);
            __syncthreads();
            buf ^= 1;
        }
    } else {
        for (int k0 = kBegin; k0 < kEnd; k0 += BK) {
            load_tiles(k0, 0);
            cp_commit();
            cp_wait<0>();
            __syncthreads();
            compute(0);
            __syncthreads();
        }
    }

    // ---- store (float2; N even, col-tail checked) ----
#pragma unroll
    for (int mf = 0; mf < MF; ++mf) {
#pragma unroll
        for (int nf = 0; nf < NF; ++nf) {
            int row = m0 + warp_m * WTM + mf * 16 + g;
            int col = n0 + warp_n * WTN + nf * 8 + tq * 2;
            if (col < N) {
                float bx = 0.f, by = 0.f;
                if (bias) { bx = bias[col]; by = bias[col + 1]; }
                float2 v0 = make_float2((float)acc[mf][nf][0] + bx, (float)acc[mf][nf][1] + by);
                float2 v1 = make_float2((float)acc[mf][nf][2] + bx, (float)acc[mf][nf][3] + by);
                *(float2*)(Cz + (size_t)row * N + col)       = v0;
                *(float2*)(Cz + (size_t)(row + 8) * N + col) = v1;
            }
        }
    }
}

// ---------------- fused split-K reduce + LN4 + gates + LN(c) + zoneout ----------------
// One CTA per batch row. Sums NS split-K partial planes in fixed order (deterministic),
// LayerNorm statistics in fp64.
template <int HU, int NS>
__global__ void __launch_bounds__(256)
pointwise_kernel(const float* __restrict__ z, size_t pstride,
                 const float* __restrict__ bias,
                 const float* __restrict__ gg, const float* __restrict__ bg,
                 const float* __restrict__ gc, const float* __restrict__ bc,
                 float* __restrict__ h, float* __restrict__ c,
                 float* __restrict__ outs /* g_outs + t*HU, or nullptr */) {
    constexpr int NTH = 256;
    __shared__ float sz[4 * HU];
    __shared__ float scp[HU];
    __shared__ double redd[16];
    __shared__ float stat[10];

    const int b = blockIdx.x, tid = threadIdx.x;
    const float* zr = z + (size_t)b * 4 * HU;

    for (int i = tid; i < 4 * HU; i += NTH) {
        float v = zr[i];
#pragma unroll
        for (int s = 1; s < NS; ++s) v += zr[s * pstride + i];
        sz[i] = v + bias[i];
    }
    __syncthreads();

    for (int ch = 0; ch < 4; ++ch) {
        double s = 0.0, q = 0.0;
        for (int i = tid; i < HU; i += NTH) {
            double v = (double)sz[ch * HU + i];
            s += v; q += v * v;
        }
#pragma unroll
        for (int o = 16; o; o >>= 1) { s += __shfl_xor_sync(~0u, s, o); q += __shfl_xor_sync(~0u, q, o); }
        if ((tid & 31) == 0) { redd[tid >> 5] = s; redd[8 + (tid >> 5)] = q; }
        __syncthreads();
        if (tid < 32) {
            double ss = (tid < 8) ? redd[tid] : 0.0;
            double qq = (tid < 8) ? redd[8 + tid] : 0.0;
#pragma unroll
            for (int o = 4; o; o >>= 1) { ss += __shfl_xor_sync(~0u, ss, o); qq += __shfl_xor_sync(~0u, qq, o); }
            if (tid == 0) {
                double mu = ss / (double)HU;
                double var = qq / (double)HU - mu * mu;
                stat[ch] = (float)mu;
                stat[4 + ch] = (float)(1.0 / sqrt(var + 1e-5));
            }
        }
        __syncthreads();
    }

    const float mu0 = stat[0], mu1 = stat[1], mu2 = stat[2], mu3 = stat[3];
    const float r0 = stat[4], r1 = stat[5], r2 = stat[6], r3 = stat[7];

    for (int i = tid; i < HU; i += NTH) {
        float iv = (sz[i]          - mu0) * r0 * gg[i]          + bg[i];
        float jv = (sz[HU + i]     - mu1) * r1 * gg[HU + i]     + bg[HU + i];
        float fv = (sz[2 * HU + i] - mu2) * r2 * gg[2 * HU + i] + bg[2 * HU + i];
        float ov = (sz[3 * HU + i] - mu3) * r3 * gg[3 * HU + i] + bg[3 * HU + i];
        float cold = c[(size_t)b * HU + i];
        float cpre = cold * sigm(fv + 1.0f) + sigm(iv) * tanhf(jv);
        scp[i] = cpre;
        sz[3 * HU + i] = ov;
    }
    __syncthreads();

    {
        double s = 0.0, q = 0.0;
        for (int i = tid; i < HU; i += NTH) {
            double v = (double)scp[i];
            s += v; q += v * v;
        }
#pragma unroll
        for (int o = 16; o; o >>= 1) { s += __shfl_xor_sync(~0u, s, o); q += __shfl_xor_sync(~0u, q, o); }
        if ((tid & 31) == 0) { redd[tid >> 5] = s; redd[8 + (tid >> 5)] = q; }
        __syncthreads();
        if (tid < 32) {
            double ss = (tid < 8) ? redd[tid] : 0.0;
            double qq = (tid < 8) ? redd[8 + tid] : 0.0;
#pragma unroll
            for (int o = 4; o; o >>= 1) { ss += __shfl_xor_sync(~0u, ss, o); qq += __shfl_xor_sync(~0u, qq, o); }
            if (tid == 0) {
                double mu = ss / (double)HU;
                double var = qq / (double)HU - mu * mu;
                stat[8] = (float)mu;
                stat[9] = (float)(1.0 / sqrt(var + 1e-5));
            }
        }
        __syncthreads();
    }
    const float muc = stat[8], rc = stat[9];

    for (int i = tid; i < HU; i += NTH) {
        float cpre = scp[i];
        float nh = tanhf((cpre - muc) * rc * gc[i] + bc[i]) * sigm(sz[3 * HU + i]);
        float hold = h[(size_t)b * HU + i];
        float cold = c[(size_t)b * HU + i];
        float hn = 0.9f * nh + 0.1f * hold;
        float cn = 0.5f * cpre + 0.5f * cold;
        h[(size_t)b * HU + i] = hn;
        c[(size_t)b * HU + i] = cn;
        if (outs) outs[(size_t)b * T_ * HU + i] = hn;
    }
}

// ---------------- init & epilogue ----------------
__global__ void zero_states_kernel() {
    int i = blockIdx.x * blockDim.x + threadIdx.x;
    if (i < B_ * F_) { g_fh[i] = 0.f; g_fc[i] = 0.f; }
    if (i < B_ * S_) { g_sh[i] = 0.f; g_sc[i] = 0.f; }
}

__global__ void copy_states_kernel(float* __restrict__ out) {
    int i = blockIdx.x * blockDim.x + threadIdx.x;
    const int NF = B_ * F_;
    const int NS = B_ * S_;
    if (i < NF)                       out[i] = g_fh[i];
    else if (i < 2 * NF)              out[i] = g_fc[i - NF];
    else if (i < 2 * NF + NS)         out[i] = g_sh[i - 2 * NF];
    else if (i < 2 * NF + 2 * NS)     out[i] = g_sc[i - 2 * NF - NS];
}

// ---------------- launch ----------------
extern "C" void kernel_launch(void* const* d_in, const int* in_sizes, int n_in,
                              void* d_out, int out_size) {
    const float* inputs = (const float*)d_in[0];
    const float* W0  = (const float*)d_in[1];
    const float* b0  = (const float*)d_in[2];
    const float* g0  = (const float*)d_in[3];
    const float* bg0 = (const float*)d_in[4];
    const float* gc0 = (const float*)d_in[5];
    const float* bc0 = (const float*)d_in[6];
    const float* W1  = (const float*)d_in[7];
    const float* b1  = (const float*)d_in[8];
    const float* g1  = (const float*)d_in[9];
    const float* bg1 = (const float*)d_in[10];
    const float* gc1 = (const float*)d_in[11];
    const float* bc1 = (const float*)d_in[12];
    const float* WS  = (const float*)d_in[13];
    const float* bS  = (const float*)d_in[14];
    const float* gS  = (const float*)d_in[15];
    const float* bgS = (const float*)d_in[16];
    const float* gcS = (const float*)d_in[17];
    const float* bcS = (const float*)d_in[18];
    const float* Wout = (const float*)d_in[19];
    const float* bout = (const float*)d_in[20];
    float* out = (float*)d_out;

    float *fh, *fc, *sh, *sc, *z, *outs;
    cudaGetSymbolAddress((void**)&fh, g_fh);
    cudaGetSymbolAddress((void**)&fc, g_fc);
    cudaGetSymbolAddress((void**)&sh, g_sh);
    cudaGetSymbolAddress((void**)&sc, g_sc);
    cudaGetSymbolAddress((void**)&z, g_z);
    cudaGetSymbolAddress((void**)&outs, g_outs);

    const size_t psF = (size_t)B_ * 4 * F_;   // fast-cell partial plane stride
    const size_t psS = (size_t)B_ * 4 * S_;   // slow-cell partial plane stride

    zero_states_kernel<<<350, 256>>>();

    for (int t = 0; t < T_; ++t) {
        // Fast cell 0: concat(x_t[128], fh[700]) @ W0 -> 4 partial planes (704 CTAs = 1 wave @5/SM)
        gemm_tf32_kernel<64, 32, 2, 2, 2, true, 4, 5><<<dim3(88, 2, 4), 128>>>(
            inputs + (size_t)t * E_, T_ * E_, E_, fh, F_, W0, nullptr, z, 4 * F_, E_ + F_, psF);
        pointwise_kernel<F_, 4><<<B_, 256>>>(z, psF, b0, g0, bg0, gc0, bc0, fh, fc, nullptr);

        // Slow cell: concat(fh[700], sh[400]) @ WS -> 7 partial planes (700 CTAs = 1 wave @5/SM)
        gemm_tf32_kernel<64, 32, 2, 2, 2, true, 7, 5><<<dim3(50, 2, 7), 128>>>(
            fh, F_, F_, sh, S_, WS, nullptr, z, 4 * S_, F_ + S_, psS);
        pointwise_kernel<S_, 7><<<B_, 256>>>(z, psS, bS, gS, bgS, gcS, bcS, sh, sc, nullptr);

        // Fast cell 1: concat(sh[400], fh[700]) @ W1 -> 4 partial planes
        gemm_tf32_kernel<64, 32, 2, 2, 2, true, 4, 5><<<dim3(88, 2, 4), 128>>>(
            sh, S_, S_, fh, F_, W1, nullptr, z, 4 * F_, S_ + F_, psF);
        pointwise_kernel<F_, 4><<<B_, 256>>>(z, psF, b1, g1, bg1, gc1, bc1, fh, fc,
                                             outs + (size_t)t * F_);
    }

    // Output projection: g_outs[12800,700] @ Wout[700,10000] + bout -> logits (single TF32)
    gemm_tf32_kernel<128, 128, 2, 4, 1, false, 1, 1><<<dim3(79, 100, 1), 256>>>(
        outs, F_, F_, outs, F_, Wout, bout, out, V_, F_, 0);

    // Final states appended after logits
    copy_states_kernel<<<1100, 256>>>(out + (size_t)B_ * T_ * V_);
}